// round 2
// baseline (speedup 1.0000x reference)
#include <cuda_runtime.h>

// ---------------- problem constants ----------------
#define NMAX 50000
#define EMAX 800000
#define D    128
#define DLAT 64
#define BN_EPS 1e-5f

// ---------------- scratch (device globals; no allocation) ----------------
__device__ float g_deg[NMAX];
__device__ float g_isd[NMAX];
__device__ float g_invdeg[NMAX];
__device__ float g_norm[EMAX];
__device__ float g_h0[(size_t)NMAX * D];   // x @ W1 (raw)
__device__ float g_h [(size_t)NMAX * D];   // conv1 output -> BN -> ReLU (in place)
__device__ float g_g [(size_t)NMAX * D];   // h @ [Wmu|Wls] (raw)
__device__ float g_sum[D];
__device__ float g_sumsq[D];
__device__ float g_scale[D];
__device__ float g_shift[D];
__device__ float g_Wcat[D * D];
__device__ float g_bcat[D];

// ---------------- init: deg=1, bn accums=0, build Wcat/bcat ----------------
__global__ void k_init(const float* __restrict__ Wmu, const float* __restrict__ Wls,
                       const float* __restrict__ bmu, const float* __restrict__ bls,
                       int N) {
    int i = blockIdx.x * blockDim.x + threadIdx.x;
    if (i < N) g_deg[i] = 1.0f;
    if (i < D) {
        g_sum[i] = 0.0f;
        g_sumsq[i] = 0.0f;
        g_bcat[i] = (i < DLAT) ? bmu[i] : bls[i - DLAT];
    }
    if (i < D * D) {
        int k = i >> 7;      // row (0..127)
        int j = i & 127;     // col (0..127)
        g_Wcat[i] = (j < DLAT) ? Wmu[k * DLAT + j] : Wls[k * DLAT + (j - DLAT)];
    }
}

// ---------------- degree count over dst (edge_index is int32!) ----------------
__global__ void k_count(const int* __restrict__ ei, int E) {
    int e = blockIdx.x * blockDim.x + threadIdx.x;
    if (e < E) atomicAdd(&g_deg[ei[E + e]], 1.0f);
}

// ---------------- finalize degree-derived quantities ----------------
__global__ void k_fin(int N) {
    int i = blockIdx.x * blockDim.x + threadIdx.x;
    if (i < N) {
        float d = g_deg[i];
        g_isd[i] = rsqrtf(d);
        g_invdeg[i] = 1.0f / d;
    }
}

// ---------------- per-edge norm ----------------
__global__ void k_norm(const int* __restrict__ ei, int E) {
    int e = blockIdx.x * blockDim.x + threadIdx.x;
    if (e < E) {
        int s = ei[e];
        int d = ei[E + e];
        g_norm[e] = g_isd[s] * g_isd[d];
    }
}

// ---------------- GEMM: C[M,128] = A[M,128] @ B[128,128] ----------------
// MODE 0: A = x (param), B = W1 (param), bias = b1 (param)
//         writes g_h0 = raw, g_h = raw*invdeg + bias      (conv1 accumulator init)
// MODE 1: A = g_h, B = g_Wcat, bias = g_bcat
//         writes g_g = raw, out_mu/out_ls = raw*invdeg + bias (conv2 accumulator init)
template <int MODE>
__global__ void __launch_bounds__(128) k_gemm(const float* __restrict__ Aext,
                                              const float* __restrict__ Bext,
                                              const float* __restrict__ bias_ext,
                                              int M,
                                              float* __restrict__ out_mu,
                                              float* __restrict__ out_ls) {
    __shared__ float As[16][68];     // transposed A tile, padded (row stride 272B, 16B-aligned)
    __shared__ float Bs[16][128];

    const float* A    = (MODE == 0) ? Aext     : g_h;
    const float* B    = (MODE == 0) ? Bext     : g_Wcat;
    const float* bias = (MODE == 0) ? bias_ext : g_bcat;

    int tid = threadIdx.x;
    int tx = tid & 15;        // 0..15 -> col group (8 cols each)
    int ty = tid >> 4;        // 0..7  -> row group (8 rows each)
    int row0 = blockIdx.x * 64;

    float acc[8][8];
#pragma unroll
    for (int i = 0; i < 8; i++)
#pragma unroll
        for (int j = 0; j < 8; j++) acc[i][j] = 0.0f;

    for (int k0 = 0; k0 < D; k0 += 16) {
        // load A tile (64 x 16), store transposed
#pragma unroll
        for (int li = 0; li < 2; li++) {
            int f = tid * 2 + li;          // 0..255
            int r = f >> 2;                // 0..63
            int kq = (f & 3) * 4;          // 0,4,8,12
            float4 v = make_float4(0.f, 0.f, 0.f, 0.f);
            if (row0 + r < M)
                v = *(const float4*)&A[(size_t)(row0 + r) * D + k0 + kq];
            As[kq + 0][r] = v.x;
            As[kq + 1][r] = v.y;
            As[kq + 2][r] = v.z;
            As[kq + 3][r] = v.w;
        }
        // load B tile (16 x 128) — contiguous rows of B
        const float4* bsrc = (const float4*)(B + (size_t)k0 * D);
#pragma unroll
        for (int j = 0; j < 4; j++)
            ((float4*)Bs)[tid + 128 * j] = bsrc[tid + 128 * j];

        __syncthreads();

#pragma unroll
        for (int k = 0; k < 16; k++) {
            float4 a0 = *(float4*)&As[k][ty * 8];
            float4 a1 = *(float4*)&As[k][ty * 8 + 4];
            float4 b0 = *(float4*)&Bs[k][tx * 8];
            float4 b1 = *(float4*)&Bs[k][tx * 8 + 4];
            float a[8] = {a0.x, a0.y, a0.z, a0.w, a1.x, a1.y, a1.z, a1.w};
            float b[8] = {b0.x, b0.y, b0.z, b0.w, b1.x, b1.y, b1.z, b1.w};
#pragma unroll
            for (int i = 0; i < 8; i++)
#pragma unroll
                for (int j = 0; j < 8; j++)
                    acc[i][j] = fmaf(a[i], b[j], acc[i][j]);
        }
        __syncthreads();
    }

    // epilogue
    int colbase = tx * 8;
    float4 bia0 = *(const float4*)&bias[colbase];
    float4 bia1 = *(const float4*)&bias[colbase + 4];

#pragma unroll
    for (int i = 0; i < 8; i++) {
        int row = row0 + ty * 8 + i;
        if (row < M) {
            float id = g_invdeg[row];
            float4 v0 = make_float4(acc[i][0], acc[i][1], acc[i][2], acc[i][3]);
            float4 v1 = make_float4(acc[i][4], acc[i][5], acc[i][6], acc[i][7]);
            float4 w0, w1;
            w0.x = fmaf(v0.x, id, bia0.x); w0.y = fmaf(v0.y, id, bia0.y);
            w0.z = fmaf(v0.z, id, bia0.z); w0.w = fmaf(v0.w, id, bia0.w);
            w1.x = fmaf(v1.x, id, bia1.x); w1.y = fmaf(v1.y, id, bia1.y);
            w1.z = fmaf(v1.z, id, bia1.z); w1.w = fmaf(v1.w, id, bia1.w);
            if (MODE == 0) {
                *(float4*)&g_h0[(size_t)row * D + colbase]     = v0;
                *(float4*)&g_h0[(size_t)row * D + colbase + 4] = v1;
                *(float4*)&g_h [(size_t)row * D + colbase]     = w0;
                *(float4*)&g_h [(size_t)row * D + colbase + 4] = w1;
            } else {
                *(float4*)&g_g[(size_t)row * D + colbase]     = v0;
                *(float4*)&g_g[(size_t)row * D + colbase + 4] = v1;
                if (colbase < DLAT) {
                    *(float4*)&out_mu[(size_t)row * DLAT + colbase]     = w0;
                    *(float4*)&out_mu[(size_t)row * DLAT + colbase + 4] = w1;
                } else {
                    *(float4*)&out_ls[(size_t)row * DLAT + colbase - DLAT]     = w0;
                    *(float4*)&out_ls[(size_t)row * DLAT + colbase - DLAT + 4] = w1;
                }
            }
        }
    }
}

// ---------------- edge aggregation (warp per edge, float4 per lane) -------
// MODE 0: g_h[dst] += norm * g_h0[src]          (128 cols)
// MODE 1: out_mu/out_ls[dst] += norm * g_g[src] (64 + 64 cols)
template <int MODE>
__global__ void k_agg(const int* __restrict__ ei, int E,
                      float* __restrict__ out_mu, float* __restrict__ out_ls) {
    int gtid = blockIdx.x * blockDim.x + threadIdx.x;
    int warp = gtid >> 5;
    int lane = gtid & 31;
    int nwarps = (gridDim.x * blockDim.x) >> 5;
    const float* feat = (MODE == 0) ? g_h0 : g_g;

    for (int e = warp; e < E; e += nwarps) {
        int s = ei[e];
        int d = ei[E + e];
        float w = g_norm[e];
        float4 v = *(const float4*)&feat[(size_t)s * D + lane * 4];
        v.x *= w; v.y *= w; v.z *= w; v.w *= w;
        float* p;
        if (MODE == 0) {
            p = &g_h[(size_t)d * D + lane * 4];
        } else {
            p = (lane < 16) ? &out_mu[(size_t)d * DLAT + lane * 4]
                            : &out_ls[(size_t)d * DLAT + (lane - 16) * 4];
        }
        atomicAdd(p + 0, v.x);
        atomicAdd(p + 1, v.y);
        atomicAdd(p + 2, v.z);
        atomicAdd(p + 3, v.w);
    }
}

// ---------------- BN statistics (sum / sumsq per column) ----------------
__global__ void k_bnstats(int N) {
    int col = threadIdx.x;  // 128 threads
    float s = 0.f, s2 = 0.f;
    for (int r = blockIdx.x; r < N; r += gridDim.x) {
        float v = g_h[(size_t)r * D + col];
        s += v;
        s2 += v * v;
    }
    atomicAdd(&g_sum[col], s);
    atomicAdd(&g_sumsq[col], s2);
}

__global__ void k_bnfin(const float* __restrict__ gamma, const float* __restrict__ beta, int N) {
    int c = threadIdx.x;
    float invN = 1.0f / (float)N;
    float mean = g_sum[c] * invN;
    float var = fmaxf(g_sumsq[c] * invN - mean * mean, 0.0f);
    float sc = gamma[c] * rsqrtf(var + BN_EPS);
    g_scale[c] = sc;
    g_shift[c] = beta[c] - mean * sc;
}

__global__ void k_bnapply(int N) {
    int i = blockIdx.x * blockDim.x + threadIdx.x;  // float4 index
    int total = N * (D / 4);
    if (i < total) {
        int c4 = i & 31;  // which float4 of the row
        float4 v = ((float4*)g_h)[i];
        float4 sc = ((float4*)g_scale)[c4];
        float4 sh = ((float4*)g_shift)[c4];
        v.x = fmaxf(fmaf(v.x, sc.x, sh.x), 0.0f);
        v.y = fmaxf(fmaf(v.y, sc.y, sh.y), 0.0f);
        v.z = fmaxf(fmaf(v.z, sc.z, sh.z), 0.0f);
        v.w = fmaxf(fmaf(v.w, sc.w, sh.w), 0.0f);
        ((float4*)g_h)[i] = v;
    }
}

// ---------------- launch ----------------
extern "C" void kernel_launch(void* const* d_in, const int* in_sizes, int n_in,
                              void* d_out, int out_size) {
    const float* x     = (const float*)d_in[0];
    const int*   ei    = (const int*)d_in[1];     // int32! (JAX default x64 disabled)
    const float* W1    = (const float*)d_in[2];
    const float* b1    = (const float*)d_in[3];
    const float* gamma = (const float*)d_in[4];
    const float* beta  = (const float*)d_in[5];
    const float* Wmu   = (const float*)d_in[6];
    const float* bmu   = (const float*)d_in[7];
    const float* Wls   = (const float*)d_in[8];
    const float* bls   = (const float*)d_in[9];

    int N = in_sizes[0] / D;
    int E = in_sizes[1] / 2;

    float* out_mu = (float*)d_out;
    float* out_ls = (float*)d_out + (size_t)N * DLAT;

    // --- degree / norm precompute ---
    k_init<<<(N + 255) / 256, 256>>>(Wmu, Wls, bmu, bls, N);
    k_count<<<(E + 255) / 256, 256>>>(ei, E);
    k_fin<<<(N + 255) / 256, 256>>>(N);
    k_norm<<<(E + 255) / 256, 256>>>(ei, E);

    // --- conv1: GEMM + init accumulator, then edge aggregation ---
    int gemm_blocks = (N + 63) / 64;
    k_gemm<0><<<gemm_blocks, 128>>>(x, W1, b1, N, nullptr, nullptr);
    k_agg<0><<<4096, 256>>>(ei, E, nullptr, nullptr);

    // --- BatchNorm (batch stats) + ReLU ---
    k_bnstats<<<512, 128>>>(N);
    k_bnfin<<<1, 128>>>(gamma, beta, N);
    k_bnapply<<<(N * (D / 4) + 255) / 256, 256>>>(N);

    // --- conv2 (mu & log_std fused): GEMM + init d_out, then aggregation ---
    k_gemm<1><<<gemm_blocks, 128>>>(nullptr, nullptr, nullptr, N, out_mu, out_ls);
    k_agg<1><<<4096, 256>>>(ei, E, out_mu, out_ls);
}

// round 4
// speedup vs baseline: 1.9522x; 1.9522x over previous
#include <cuda_runtime.h>

// ---------------- problem constants ----------------
#define NMAX 50000
#define EMAX 800000
#define D    128
#define DLAT 64
#define BN_EPS 1e-5f

// ---------------- scratch (device globals; no allocation) ----------------
__device__ int   g_cnt[NMAX];          // in-degree counts (excl. self loop)
__device__ int   g_rowptr[NMAX + 1];   // CSR row pointers (by dst)
__device__ int   g_cursor[NMAX];       // scatter cursors
__device__ int   g_srcs[EMAX];         // CSR column indices (src nodes)
__device__ float g_w[EMAX];            // per-edge norm (sorted by dst)
__device__ float g_isd[NMAX];          // 1/sqrt(deg)
__device__ float g_invdeg[NMAX];       // 1/deg
__device__ float g_h0[(size_t)NMAX * D];    // x @ W1 (raw)
__device__ float g_h [(size_t)NMAX * D];    // conv1 out -> BN+ReLU (in place)
__device__ float g_aggh[(size_t)NMAX * D];  // aggregated h (conv2 pre-GEMM)
__device__ float g_sum[D];
__device__ float g_sumsq[D];
__device__ float g_scale[D];
__device__ float g_shift[D];
__device__ float g_Wcat[D * D];
__device__ float g_bcat[D];

// ---------------- init: zero counters/accums, build Wcat/bcat ----------------
// MUST be launched with >= max(N, D*D) threads: it resets g_cnt[0..N) each call.
__global__ void k_init(const float* __restrict__ Wmu, const float* __restrict__ Wls,
                       const float* __restrict__ bmu, const float* __restrict__ bls,
                       int N) {
    int i = blockIdx.x * blockDim.x + threadIdx.x;
    if (i < N) g_cnt[i] = 0;
    if (i < D) {
        g_sum[i] = 0.0f;
        g_sumsq[i] = 0.0f;
        g_bcat[i] = (i < DLAT) ? bmu[i] : bls[i - DLAT];
    }
    if (i < D * D) {
        int k = i >> 7;      // row
        int j = i & 127;     // col
        g_Wcat[i] = (j < DLAT) ? Wmu[k * DLAT + j] : Wls[k * DLAT + (j - DLAT)];
    }
}

// ---------------- degree count over dst ----------------
__global__ void k_count(const int* __restrict__ ei, int E) {
    int e = blockIdx.x * blockDim.x + threadIdx.x;
    if (e < E) atomicAdd(&g_cnt[ei[E + e]], 1);
}

// ---------------- degree-derived quantities ----------------
__global__ void k_fin(int N) {
    int i = blockIdx.x * blockDim.x + threadIdx.x;
    if (i < N) {
        float d = (float)g_cnt[i] + 1.0f;   // + self loop
        g_isd[i] = rsqrtf(d);
        g_invdeg[i] = 1.0f / d;
    }
}

// ---------------- single-block exclusive prefix scan over g_cnt ----------------
__global__ void __launch_bounds__(1024) k_scan(int N, int E) {
    __shared__ int warpsums[32];
    int tid = threadIdx.x;
    int lane = tid & 31, wid = tid >> 5;
    int chunk = (N + 1023) / 1024;
    int beg = min(tid * chunk, N);
    int end = min(beg + chunk, N);

    int s = 0;
    for (int i = beg; i < end; i++) s += g_cnt[i];

    // warp inclusive scan
    int v = s;
#pragma unroll
    for (int o = 1; o < 32; o <<= 1) {
        int n = __shfl_up_sync(0xffffffffu, v, o);
        if (lane >= o) v += n;
    }
    if (lane == 31) warpsums[wid] = v;
    __syncthreads();
    if (wid == 0) {
        int t = warpsums[lane];
#pragma unroll
        for (int o = 1; o < 32; o <<= 1) {
            int n = __shfl_up_sync(0xffffffffu, t, o);
            if (lane >= o) t += n;
        }
        warpsums[lane] = t;
    }
    __syncthreads();
    int ex = v - s + (wid > 0 ? warpsums[wid - 1] : 0);

    int run = ex;
    for (int i = beg; i < end; i++) {
        g_rowptr[i] = run;
        g_cursor[i] = run;
        run += g_cnt[i];
    }
    if (tid == 1023) g_rowptr[N] = run;   // == E
}

// ---------------- scatter edges into CSR slots ----------------
__global__ void k_scatter(const int* __restrict__ ei, int E) {
    int e = blockIdx.x * blockDim.x + threadIdx.x;
    if (e < E) {
        int s = ei[e];
        int d = ei[E + e];
        int pos = atomicAdd(&g_cursor[d], 1);
        g_srcs[pos] = s;
        g_w[pos] = g_isd[s] * g_isd[d];
    }
}

// ---------------- GEMM: C[M,128] = A[M,128] @ B[128,128] ----------------
// MODE 0: A=x, B=W1           -> g_h0 = raw
// MODE 1: A=g_aggh, B=g_Wcat  -> out_mu / out_ls = raw + bcat (split)
template <int MODE>
__global__ void __launch_bounds__(128) k_gemm(const float* __restrict__ Aext,
                                              const float* __restrict__ Bext,
                                              int M,
                                              float* __restrict__ out_mu,
                                              float* __restrict__ out_ls) {
    __shared__ float As[16][68];
    __shared__ float Bs[16][128];

    const float* A = (MODE == 0) ? Aext : g_aggh;
    const float* B = (MODE == 0) ? Bext : g_Wcat;

    int tid = threadIdx.x;
    int tx = tid & 15;
    int ty = tid >> 4;
    int row0 = blockIdx.x * 64;

    float acc[8][8];
#pragma unroll
    for (int i = 0; i < 8; i++)
#pragma unroll
        for (int j = 0; j < 8; j++) acc[i][j] = 0.0f;

    for (int k0 = 0; k0 < D; k0 += 16) {
#pragma unroll
        for (int li = 0; li < 2; li++) {
            int f = tid * 2 + li;
            int r = f >> 2;
            int kq = (f & 3) * 4;
            float4 v = make_float4(0.f, 0.f, 0.f, 0.f);
            if (row0 + r < M)
                v = *(const float4*)&A[(size_t)(row0 + r) * D + k0 + kq];
            As[kq + 0][r] = v.x;
            As[kq + 1][r] = v.y;
            As[kq + 2][r] = v.z;
            As[kq + 3][r] = v.w;
        }
        const float4* bsrc = (const float4*)(B + (size_t)k0 * D);
#pragma unroll
        for (int j = 0; j < 4; j++)
            ((float4*)Bs)[tid + 128 * j] = bsrc[tid + 128 * j];

        __syncthreads();

#pragma unroll
        for (int k = 0; k < 16; k++) {
            float4 a0 = *(float4*)&As[k][ty * 8];
            float4 a1 = *(float4*)&As[k][ty * 8 + 4];
            float4 b0 = *(float4*)&Bs[k][tx * 8];
            float4 b1 = *(float4*)&Bs[k][tx * 8 + 4];
            float a[8] = {a0.x, a0.y, a0.z, a0.w, a1.x, a1.y, a1.z, a1.w};
            float b[8] = {b0.x, b0.y, b0.z, b0.w, b1.x, b1.y, b1.z, b1.w};
#pragma unroll
            for (int i = 0; i < 8; i++)
#pragma unroll
                for (int j = 0; j < 8; j++)
                    acc[i][j] = fmaf(a[i], b[j], acc[i][j]);
        }
        __syncthreads();
    }

    int colbase = tx * 8;
#pragma unroll
    for (int i = 0; i < 8; i++) {
        int row = row0 + ty * 8 + i;
        if (row < M) {
            float4 v0 = make_float4(acc[i][0], acc[i][1], acc[i][2], acc[i][3]);
            float4 v1 = make_float4(acc[i][4], acc[i][5], acc[i][6], acc[i][7]);
            if (MODE == 0) {
                *(float4*)&g_h0[(size_t)row * D + colbase]     = v0;
                *(float4*)&g_h0[(size_t)row * D + colbase + 4] = v1;
            } else {
                float4 bi0 = *(const float4*)&g_bcat[colbase];
                float4 bi1 = *(const float4*)&g_bcat[colbase + 4];
                v0.x += bi0.x; v0.y += bi0.y; v0.z += bi0.z; v0.w += bi0.w;
                v1.x += bi1.x; v1.y += bi1.y; v1.z += bi1.z; v1.w += bi1.w;
                if (colbase < DLAT) {
                    *(float4*)&out_mu[(size_t)row * DLAT + colbase]     = v0;
                    *(float4*)&out_mu[(size_t)row * DLAT + colbase + 4] = v1;
                } else {
                    *(float4*)&out_ls[(size_t)row * DLAT + colbase - DLAT]     = v0;
                    *(float4*)&out_ls[(size_t)row * DLAT + colbase - DLAT + 4] = v1;
                }
            }
        }
    }
}

// ---------------- CSR aggregation: warp per node, no output atomics -------
// MODE 0: g_h[i]   = sum_e w*g_h0[src] + invdeg[i]*g_h0[i] + b1  (+ fused BN partials)
// MODE 1: g_aggh[i]= sum_e w*g_h [src] + invdeg[i]*g_h [i]
template <int MODE>
__global__ void __launch_bounds__(256) k_agg(const float* __restrict__ b1, int N) {
    __shared__ float sh_s[D];
    __shared__ float sh_s2[D];
    if (MODE == 0) {
        if (threadIdx.x < D) { sh_s[threadIdx.x] = 0.f; sh_s2[threadIdx.x] = 0.f; }
        __syncthreads();
    }

    int gwarp = (blockIdx.x * blockDim.x + threadIdx.x) >> 5;
    int lane = threadIdx.x & 31;
    const float* feat = (MODE == 0) ? g_h0 : g_h;

    float4 acc = make_float4(0.f, 0.f, 0.f, 0.f);
    bool active = (gwarp < N);
    if (active) {
        int node = gwarp;
        int beg = g_rowptr[node];
        int end = g_rowptr[node + 1];
        float id = g_invdeg[node];

        float4 self = *(const float4*)&feat[(size_t)node * D + lane * 4];
        acc.x = self.x * id; acc.y = self.y * id;
        acc.z = self.z * id; acc.w = self.w * id;
        if (MODE == 0) {
            float4 bi = *(const float4*)&b1[lane * 4];
            acc.x += bi.x; acc.y += bi.y; acc.z += bi.z; acc.w += bi.w;
        }

        for (int base = beg; base < end; base += 32) {
            int t = base + lane;
            int s = 0; float w = 0.f;
            if (t < end) { s = g_srcs[t]; w = g_w[t]; }
            int m = min(32, end - base);
            for (int j = 0; j < m; j++) {
                int sj = __shfl_sync(0xffffffffu, s, j);
                float wj = __shfl_sync(0xffffffffu, w, j);
                const float4 v = *(const float4*)&feat[(size_t)sj * D + lane * 4];
                acc.x = fmaf(wj, v.x, acc.x);
                acc.y = fmaf(wj, v.y, acc.y);
                acc.z = fmaf(wj, v.z, acc.z);
                acc.w = fmaf(wj, v.w, acc.w);
            }
        }

        float* out = (MODE == 0) ? g_h : g_aggh;
        *(float4*)&out[(size_t)gwarp * D + lane * 4] = acc;
    }

    if (MODE == 0) {
        if (active) {
            int c = lane * 4;
            atomicAdd(&sh_s[c + 0], acc.x);  atomicAdd(&sh_s2[c + 0], acc.x * acc.x);
            atomicAdd(&sh_s[c + 1], acc.y);  atomicAdd(&sh_s2[c + 1], acc.y * acc.y);
            atomicAdd(&sh_s[c + 2], acc.z);  atomicAdd(&sh_s2[c + 2], acc.z * acc.z);
            atomicAdd(&sh_s[c + 3], acc.w);  atomicAdd(&sh_s2[c + 3], acc.w * acc.w);
        }
        __syncthreads();
        if (threadIdx.x < D) {
            atomicAdd(&g_sum[threadIdx.x], sh_s[threadIdx.x]);
            atomicAdd(&g_sumsq[threadIdx.x], sh_s2[threadIdx.x]);
        }
    }
}

// ---------------- BN finalize + apply (ReLU) ----------------
__global__ void k_bnfin(const float* __restrict__ gamma, const float* __restrict__ beta, int N) {
    int c = threadIdx.x;
    float invN = 1.0f / (float)N;
    float mean = g_sum[c] * invN;
    float var = fmaxf(g_sumsq[c] * invN - mean * mean, 0.0f);
    float sc = gamma[c] * rsqrtf(var + BN_EPS);
    g_scale[c] = sc;
    g_shift[c] = beta[c] - mean * sc;
}

__global__ void k_bnapply(int N) {
    int i = blockIdx.x * blockDim.x + threadIdx.x;  // float4 index
    int total = N * (D / 4);
    if (i < total) {
        int c4 = i & 31;
        float4 v = ((float4*)g_h)[i];
        float4 sc = ((float4*)g_scale)[c4];
        float4 sh = ((float4*)g_shift)[c4];
        v.x = fmaxf(fmaf(v.x, sc.x, sh.x), 0.0f);
        v.y = fmaxf(fmaf(v.y, sc.y, sh.y), 0.0f);
        v.z = fmaxf(fmaf(v.z, sc.z, sh.z), 0.0f);
        v.w = fmaxf(fmaf(v.w, sc.w, sh.w), 0.0f);
        ((float4*)g_h)[i] = v;
    }
}

// ---------------- launch ----------------
extern "C" void kernel_launch(void* const* d_in, const int* in_sizes, int n_in,
                              void* d_out, int out_size) {
    const float* x     = (const float*)d_in[0];
    const int*   ei    = (const int*)d_in[1];     // int32
    const float* W1    = (const float*)d_in[2];
    const float* b1    = (const float*)d_in[3];
    const float* gamma = (const float*)d_in[4];
    const float* beta  = (const float*)d_in[5];
    const float* Wmu   = (const float*)d_in[6];
    const float* bmu   = (const float*)d_in[7];
    const float* Wls   = (const float*)d_in[8];
    const float* bls   = (const float*)d_in[9];

    int N = in_sizes[0] / D;
    int E = in_sizes[1] / 2;

    float* out_mu = (float*)d_out;
    float* out_ls = (float*)d_out + (size_t)N * DLAT;

    // --- CSR build + degree precompute ---
    int init_threads = (N > D * D) ? N : D * D;   // cover BOTH g_cnt[N] and g_Wcat[D*D]
    k_init<<<(init_threads + 255) / 256, 256>>>(Wmu, Wls, bmu, bls, N);
    k_count<<<(E + 255) / 256, 256>>>(ei, E);
    k_fin<<<(N + 255) / 256, 256>>>(N);
    k_scan<<<1, 1024>>>(N, E);
    k_scatter<<<(E + 255) / 256, 256>>>(ei, E);

    // --- conv1: GEMM then CSR-gather aggregation (+fused BN stats) ---
    int gemm_blocks = (N + 63) / 64;
    k_gemm<0><<<gemm_blocks, 128>>>(x, W1, N, nullptr, nullptr);
    int agg_blocks = (N + 7) / 8;   // 8 warps (nodes) per 256-thread block
    k_agg<0><<<agg_blocks, 256>>>(b1, N);

    // --- BatchNorm finalize + apply + ReLU ---
    k_bnfin<<<1, 128>>>(gamma, beta, N);
    k_bnapply<<<(N * (D / 4) + 255) / 256, 256>>>(N);

    // --- conv2: aggregate h first (linearity), then fused [Wmu|Wls] GEMM ---
    k_agg<1><<<agg_blocks, 256>>>(nullptr, N);
    k_gemm<1><<<gemm_blocks, 128>>>(nullptr, nullptr, N, out_mu, out_ls);
}

// round 5
// speedup vs baseline: 2.5460x; 1.3042x over previous
#include <cuda_runtime.h>

// ---------------- problem constants ----------------
#define NMAX 50000
#define EMAX 800000
#define D    128
#define DLAT 64
#define BN_EPS 1e-5f
#define SCAN_B 256
#define NBLK ((NMAX + SCAN_B - 1) / SCAN_B)

// ---------------- scratch (device globals; no allocation) ----------------
__device__ int   g_cnt[NMAX];          // in-degree counts (excl. self loop)
__device__ int   g_rowptr[NMAX + 1];   // CSR row pointers (by dst)
__device__ int   g_cursor[NMAX];       // scatter cursors
__device__ int   g_srcs[EMAX];         // CSR column indices (src nodes)
__device__ float g_w[EMAX];            // per-edge norm (CSR order)
__device__ int   g_bsum[NBLK];         // per-block count sums
__device__ int   g_boff[NBLK];         // per-block exclusive offsets
__device__ float g_isd[NMAX];          // 1/sqrt(deg)
__device__ float g_invdeg[NMAX];       // 1/deg
__device__ float g_h0[(size_t)NMAX * D];    // x @ W1 (raw)
__device__ float g_h [(size_t)NMAX * D];    // conv1 out -> BN+ReLU (in place)
__device__ float g_aggh[(size_t)NMAX * D];  // aggregated h (conv2 pre-GEMM)
__device__ float g_sum[D];
__device__ float g_sumsq[D];
__device__ float g_scale[D];
__device__ float g_shift[D];
__device__ float g_Wcat[D * D];
__device__ float g_bcat[D];

// ---------------- init: zero counters/accums, build Wcat/bcat ----------------
// MUST cover max(N, D*D) threads.
__global__ void k_init(const float* __restrict__ Wmu, const float* __restrict__ Wls,
                       const float* __restrict__ bmu, const float* __restrict__ bls,
                       int N) {
    int i = blockIdx.x * blockDim.x + threadIdx.x;
    if (i < N) g_cnt[i] = 0;
    if (i < D) {
        g_sum[i] = 0.0f;
        g_sumsq[i] = 0.0f;
        g_bcat[i] = (i < DLAT) ? bmu[i] : bls[i - DLAT];
    }
    if (i < D * D) {
        int k = i >> 7;
        int j = i & 127;
        g_Wcat[i] = (j < DLAT) ? Wmu[k * DLAT + j] : Wls[k * DLAT + (j - DLAT)];
    }
}

// ---------------- degree count over dst ----------------
__global__ void k_count(const int* __restrict__ ei, int E) {
    int e = blockIdx.x * blockDim.x + threadIdx.x;
    if (e < E) atomicAdd(&g_cnt[ei[E + e]], 1);
}

// ---------------- scan phase A: block sums + degree-derived values ----------
__global__ void __launch_bounds__(SCAN_B) k_scanA(int N) {
    __shared__ int ws[8];
    int i = blockIdx.x * SCAN_B + threadIdx.x;
    int v = (i < N) ? g_cnt[i] : 0;
    if (i < N) {
        float d = (float)v + 1.0f;   // + self loop
        g_isd[i] = rsqrtf(d);
        g_invdeg[i] = 1.0f / d;
    }
    int lane = threadIdx.x & 31, wid = threadIdx.x >> 5;
    int r = v;
#pragma unroll
    for (int o = 16; o; o >>= 1) r += __shfl_down_sync(0xffffffffu, r, o);
    if (lane == 0) ws[wid] = r;
    __syncthreads();
    if (threadIdx.x < 8) {
        int t = ws[threadIdx.x];
#pragma unroll
        for (int o = 4; o; o >>= 1) t += __shfl_down_sync(0xffu, t, o);
        if (threadIdx.x == 0) g_bsum[blockIdx.x] = t;
    }
}

// ---------------- scan phase B: exclusive scan of block sums (nb<=256) ------
__global__ void __launch_bounds__(SCAN_B) k_scanB(int nb, int E, int N) {
    __shared__ int ws[8];
    int tid = threadIdx.x;
    int v = (tid < nb) ? g_bsum[tid] : 0;
    int lane = tid & 31, wid = tid >> 5;
    int x = v;
#pragma unroll
    for (int o = 1; o < 32; o <<= 1) {
        int n = __shfl_up_sync(0xffffffffu, x, o);
        if (lane >= o) x += n;
    }
    if (lane == 31) ws[wid] = x;
    __syncthreads();
    if (wid == 0 && lane < 8) {
        int t = ws[lane];
#pragma unroll
        for (int o = 1; o < 8; o <<= 1) {
            int n = __shfl_up_sync(0xffu, t, o);
            if (lane >= o) t += n;
        }
        ws[lane] = t;
    }
    __syncthreads();
    int incl = x + (wid > 0 ? ws[wid - 1] : 0);
    if (tid < nb) g_boff[tid] = incl - v;
    if (tid == 0) g_rowptr[N] = E;
}

// ---------------- scan phase C: local exclusive scan + offset ---------------
__global__ void __launch_bounds__(SCAN_B) k_scanC(int N) {
    __shared__ int ws[8];
    int i = blockIdx.x * SCAN_B + threadIdx.x;
    int v = (i < N) ? g_cnt[i] : 0;
    int lane = threadIdx.x & 31, wid = threadIdx.x >> 5;
    int x = v;
#pragma unroll
    for (int o = 1; o < 32; o <<= 1) {
        int n = __shfl_up_sync(0xffffffffu, x, o);
        if (lane >= o) x += n;
    }
    if (lane == 31) ws[wid] = x;
    __syncthreads();
    if (wid == 0 && lane < 8) {
        int t = ws[lane];
#pragma unroll
        for (int o = 1; o < 8; o <<= 1) {
            int n = __shfl_up_sync(0xffu, t, o);
            if (lane >= o) t += n;
        }
        ws[lane] = t;
    }
    __syncthreads();
    int ex = x - v + (wid > 0 ? ws[wid - 1] : 0) + g_boff[blockIdx.x];
    if (i < N) {
        g_rowptr[i] = ex;
        g_cursor[i] = ex;
    }
}

// ---------------- scatter edges into CSR slots ----------------
__global__ void k_scatter(const int* __restrict__ ei, int E) {
    int e = blockIdx.x * blockDim.x + threadIdx.x;
    if (e < E) {
        int s = ei[e];
        int d = ei[E + e];
        int pos = atomicAdd(&g_cursor[d], 1);
        g_srcs[pos] = s;
        g_w[pos] = g_isd[s] * g_isd[d];
    }
}

// ---------------- GEMM: C[M,128] = A[M,128] @ B[128,128] ----------------
// MODE 0: A=x, B=W1           -> g_h0 = raw
// MODE 1: A=g_aggh, B=g_Wcat  -> out_mu / out_ls = raw + bcat (split)
template <int MODE>
__global__ void __launch_bounds__(128) k_gemm(const float* __restrict__ Aext,
                                              const float* __restrict__ Bext,
                                              int M,
                                              float* __restrict__ out_mu,
                                              float* __restrict__ out_ls) {
    __shared__ float As[16][68];
    __shared__ float Bs[16][128];

    const float* A = (MODE == 0) ? Aext : g_aggh;
    const float* B = (MODE == 0) ? Bext : g_Wcat;

    int tid = threadIdx.x;
    int tx = tid & 15;
    int ty = tid >> 4;
    int row0 = blockIdx.x * 64;

    float acc[8][8];
#pragma unroll
    for (int i = 0; i < 8; i++)
#pragma unroll
        for (int j = 0; j < 8; j++) acc[i][j] = 0.0f;

    for (int k0 = 0; k0 < D; k0 += 16) {
#pragma unroll
        for (int li = 0; li < 2; li++) {
            int f = tid * 2 + li;
            int r = f >> 2;
            int kq = (f & 3) * 4;
            float4 v = make_float4(0.f, 0.f, 0.f, 0.f);
            if (row0 + r < M)
                v = *(const float4*)&A[(size_t)(row0 + r) * D + k0 + kq];
            As[kq + 0][r] = v.x;
            As[kq + 1][r] = v.y;
            As[kq + 2][r] = v.z;
            As[kq + 3][r] = v.w;
        }
        const float4* bsrc = (const float4*)(B + (size_t)k0 * D);
#pragma unroll
        for (int j = 0; j < 4; j++)
            ((float4*)Bs)[tid + 128 * j] = bsrc[tid + 128 * j];

        __syncthreads();

#pragma unroll
        for (int k = 0; k < 16; k++) {
            float4 a0 = *(float4*)&As[k][ty * 8];
            float4 a1 = *(float4*)&As[k][ty * 8 + 4];
            float4 b0 = *(float4*)&Bs[k][tx * 8];
            float4 b1 = *(float4*)&Bs[k][tx * 8 + 4];
            float a[8] = {a0.x, a0.y, a0.z, a0.w, a1.x, a1.y, a1.z, a1.w};
            float b[8] = {b0.x, b0.y, b0.z, b0.w, b1.x, b1.y, b1.z, b1.w};
#pragma unroll
            for (int i = 0; i < 8; i++)
#pragma unroll
                for (int j = 0; j < 8; j++)
                    acc[i][j] = fmaf(a[i], b[j], acc[i][j]);
        }
        __syncthreads();
    }

    int colbase = tx * 8;
#pragma unroll
    for (int i = 0; i < 8; i++) {
        int row = row0 + ty * 8 + i;
        if (row < M) {
            float4 v0 = make_float4(acc[i][0], acc[i][1], acc[i][2], acc[i][3]);
            float4 v1 = make_float4(acc[i][4], acc[i][5], acc[i][6], acc[i][7]);
            if (MODE == 0) {
                *(float4*)&g_h0[(size_t)row * D + colbase]     = v0;
                *(float4*)&g_h0[(size_t)row * D + colbase + 4] = v1;
            } else {
                float4 bi0 = *(const float4*)&g_bcat[colbase];
                float4 bi1 = *(const float4*)&g_bcat[colbase + 4];
                v0.x += bi0.x; v0.y += bi0.y; v0.z += bi0.z; v0.w += bi0.w;
                v1.x += bi1.x; v1.y += bi1.y; v1.z += bi1.z; v1.w += bi1.w;
                if (colbase < DLAT) {
                    *(float4*)&out_mu[(size_t)row * DLAT + colbase]     = v0;
                    *(float4*)&out_mu[(size_t)row * DLAT + colbase + 4] = v1;
                } else {
                    *(float4*)&out_ls[(size_t)row * DLAT + colbase - DLAT]     = v0;
                    *(float4*)&out_ls[(size_t)row * DLAT + colbase - DLAT + 4] = v1;
                }
            }
        }
    }
}

// ---------------- CSR aggregation: warp per node, no output atomics -------
// MODE 0: g_h[i]   = sum_e w*g_h0[src] + invdeg[i]*g_h0[i] + b1  (+ fused BN partials)
// MODE 1: g_aggh[i]= sum_e w*g_h [src] + invdeg[i]*g_h [i]
template <int MODE>
__global__ void __launch_bounds__(256) k_agg(const float* __restrict__ b1, int N) {
    __shared__ float sh_s[D];
    __shared__ float sh_s2[D];
    if (MODE == 0) {
        if (threadIdx.x < D) { sh_s[threadIdx.x] = 0.f; sh_s2[threadIdx.x] = 0.f; }
        __syncthreads();
    }

    int gwarp = (blockIdx.x * blockDim.x + threadIdx.x) >> 5;
    int lane = threadIdx.x & 31;
    const float* feat = (MODE == 0) ? g_h0 : g_h;

    float4 acc = make_float4(0.f, 0.f, 0.f, 0.f);
    bool active = (gwarp < N);
    if (active) {
        int node = gwarp;
        int beg = g_rowptr[node];
        int end = g_rowptr[node + 1];
        float id = g_invdeg[node];

        float4 self = *(const float4*)&feat[(size_t)node * D + lane * 4];
        acc.x = self.x * id; acc.y = self.y * id;
        acc.z = self.z * id; acc.w = self.w * id;
        if (MODE == 0) {
            float4 bi = *(const float4*)&b1[lane * 4];
            acc.x += bi.x; acc.y += bi.y; acc.z += bi.z; acc.w += bi.w;
        }

        for (int base = beg; base < end; base += 32) {
            int t = base + lane;
            int s = 0; float w = 0.f;
            if (t < end) { s = g_srcs[t]; w = g_w[t]; }
            int m = min(32, end - base);
            for (int j = 0; j < m; j++) {
                int sj = __shfl_sync(0xffffffffu, s, j);
                float wj = __shfl_sync(0xffffffffu, w, j);
                const float4 v = *(const float4*)&feat[(size_t)sj * D + lane * 4];
                acc.x = fmaf(wj, v.x, acc.x);
                acc.y = fmaf(wj, v.y, acc.y);
                acc.z = fmaf(wj, v.z, acc.z);
                acc.w = fmaf(wj, v.w, acc.w);
            }
        }

        float* out = (MODE == 0) ? g_h : g_aggh;
        *(float4*)&out[(size_t)gwarp * D + lane * 4] = acc;
    }

    if (MODE == 0) {
        if (active) {
            int c = lane * 4;
            atomicAdd(&sh_s[c + 0], acc.x);  atomicAdd(&sh_s2[c + 0], acc.x * acc.x);
            atomicAdd(&sh_s[c + 1], acc.y);  atomicAdd(&sh_s2[c + 1], acc.y * acc.y);
            atomicAdd(&sh_s[c + 2], acc.z);  atomicAdd(&sh_s2[c + 2], acc.z * acc.z);
            atomicAdd(&sh_s[c + 3], acc.w);  atomicAdd(&sh_s2[c + 3], acc.w * acc.w);
        }
        __syncthreads();
        if (threadIdx.x < D) {
            atomicAdd(&g_sum[threadIdx.x], sh_s[threadIdx.x]);
            atomicAdd(&g_sumsq[threadIdx.x], sh_s2[threadIdx.x]);
        }
    }
}

// ---------------- BN finalize + apply (ReLU) ----------------
__global__ void k_bnfin(const float* __restrict__ gamma, const float* __restrict__ beta, int N) {
    int c = threadIdx.x;
    float invN = 1.0f / (float)N;
    float mean = g_sum[c] * invN;
    float var = fmaxf(g_sumsq[c] * invN - mean * mean, 0.0f);
    float sc = gamma[c] * rsqrtf(var + BN_EPS);
    g_scale[c] = sc;
    g_shift[c] = beta[c] - mean * sc;
}

__global__ void k_bnapply(int N) {
    int i = blockIdx.x * blockDim.x + threadIdx.x;  // float4 index
    int total = N * (D / 4);
    if (i < total) {
        int c4 = i & 31;
        float4 v = ((float4*)g_h)[i];
        float4 sc = ((float4*)g_scale)[c4];
        float4 sh = ((float4*)g_shift)[c4];
        v.x = fmaxf(fmaf(v.x, sc.x, sh.x), 0.0f);
        v.y = fmaxf(fmaf(v.y, sc.y, sh.y), 0.0f);
        v.z = fmaxf(fmaf(v.z, sc.z, sh.z), 0.0f);
        v.w = fmaxf(fmaf(v.w, sc.w, sh.w), 0.0f);
        ((float4*)g_h)[i] = v;
    }
}

// ---------------- launch ----------------
extern "C" void kernel_launch(void* const* d_in, const int* in_sizes, int n_in,
                              void* d_out, int out_size) {
    const float* x     = (const float*)d_in[0];
    const int*   ei    = (const int*)d_in[1];     // int32
    const float* W1    = (const float*)d_in[2];
    const float* b1    = (const float*)d_in[3];
    const float* gamma = (const float*)d_in[4];
    const float* beta  = (const float*)d_in[5];
    const float* Wmu   = (const float*)d_in[6];
    const float* bmu   = (const float*)d_in[7];
    const float* Wls   = (const float*)d_in[8];
    const float* bls   = (const float*)d_in[9];

    int N = in_sizes[0] / D;
    int E = in_sizes[1] / 2;

    float* out_mu = (float*)d_out;
    float* out_ls = (float*)d_out + (size_t)N * DLAT;

    // --- CSR build + degree precompute (hierarchical parallel scan) ---
    int init_threads = (N > D * D) ? N : D * D;
    k_init<<<(init_threads + 255) / 256, 256>>>(Wmu, Wls, bmu, bls, N);
    k_count<<<(E + 255) / 256, 256>>>(ei, E);
    int nb = (N + SCAN_B - 1) / SCAN_B;
    k_scanA<<<nb, SCAN_B>>>(N);
    k_scanB<<<1, SCAN_B>>>(nb, E, N);
    k_scanC<<<nb, SCAN_B>>>(N);
    k_scatter<<<(E + 255) / 256, 256>>>(ei, E);

    // --- conv1: GEMM then CSR-gather aggregation (+fused BN stats) ---
    int gemm_blocks = (N + 63) / 64;
    k_gemm<0><<<gemm_blocks, 128>>>(x, W1, N, nullptr, nullptr);
    int agg_blocks = (N + 7) / 8;
    k_agg<0><<<agg_blocks, 256>>>(b1, N);

    // --- BatchNorm finalize + apply + ReLU ---
    k_bnfin<<<1, 128>>>(gamma, beta, N);
    k_bnapply<<<(N * (D / 4) + 255) / 256, 256>>>(N);

    // --- conv2: aggregate h first (linearity), then fused [Wmu|Wls] GEMM ---
    k_agg<1><<<agg_blocks, 256>>>(nullptr, N);
    k_gemm<1><<<gemm_blocks, 128>>>(nullptr, nullptr, N, out_mu, out_ls);
}